// round 3
// baseline (speedup 1.0000x reference)
#include <cuda_runtime.h>
#include <cstdint>

#define B_    16
#define CIN   512
#define COUT  512
#define DLAT  512
#define Hs    64
#define Ws    64

#define LIN_COEF  0.04419417382415922f    // 1/sqrt(512)
#define CONV_COEF 0.014731391274719742f   // 1/sqrt(512*9)

// ---- scratch (device globals; no allocation allowed) ----
__device__ float g_mod[B_ * CIN];          // conv_coef * style[b][i]
__device__ float g_sig[B_ * COUT];         // sigma_inv[b][o]
__device__ float g_cwt[CIN * 9 * COUT];    // conv_w transposed to [i][tap][o]
__device__ float g_wsqT[CIN * COUT];       // sum_taps conv_w^2, layout [i][o]

// ============================================================
// K1: mod[b][i] = (dot(w[b,:], style_w[i,:]) * LIN + style_b[i]) * CONV
// grid 32 (16 i-rows each), block 256 (16 b x 16 i)
// ============================================================
__global__ __launch_bounds__(256) void k_style(
    const float* __restrict__ w, const float* __restrict__ sw,
    const float* __restrict__ sb)
{
    __shared__ float s_sw[16][DLAT + 1];
    int i0 = blockIdx.x * 16;
    for (int idx = threadIdx.x; idx < 16 * DLAT; idx += 256) {
        int r = idx / DLAT, d = idx % DLAT;
        s_sw[r][d] = sw[(i0 + r) * DLAT + d];
    }
    __syncthreads();
    int t = threadIdx.x;
    int b = t >> 4, il = t & 15;
    const float* wb = w + b * DLAT;
    float acc = 0.f;
    for (int d = 0; d < DLAT; d++) acc += __ldg(&wb[d]) * s_sw[il][d];
    int i = i0 + il;
    g_mod[b * CIN + i] = (acc * LIN_COEF + sb[i]) * CONV_COEF;
}

// ============================================================
// K2a: transpose conv_w [O][I][3][3] -> g_cwt [I][tap][O]
// grid (9, 512) = (tap, i), block 512 (o)
// ============================================================
__global__ __launch_bounds__(512) void k_transpose(const float* __restrict__ cw)
{
    int tap = blockIdx.x;
    int i   = blockIdx.y;
    int o   = threadIdx.x;
    g_cwt[(i * 9 + tap) * COUT + o] = cw[(o * CIN + i) * 9 + tap];
}

// ============================================================
// K2b: wsqT[i][o] = sum_tap cwt[i][tap][o]^2
// grid 512 (i), block 512 (o)
// ============================================================
__global__ __launch_bounds__(512) void k_wsq()
{
    int i = blockIdx.x, o = threadIdx.x;
    float s = 0.f;
#pragma unroll
    for (int tap = 0; tap < 9; tap++) {
        float v = g_cwt[(i * 9 + tap) * COUT + o];
        s += v * v;
    }
    g_wsqT[i * COUT + o] = s;
}

// ============================================================
// K3: sig[b][o] = rsqrt( sum_i mod[b][i]^2 * wsqT[i][o] + eps )
// grid 16 (b), block 512 (o)
// ============================================================
__global__ __launch_bounds__(512) void k_sig()
{
    __shared__ float m2[CIN];
    int b = blockIdx.x, o = threadIdx.x;
    for (int i = threadIdx.x; i < CIN; i += 512) {
        float m = g_mod[b * CIN + i];
        m2[i] = m * m;
    }
    __syncthreads();
    float s = 0.f;
    for (int i = 0; i < CIN; i++) s += m2[i] * g_wsqT[i * COUT + o];
    g_sig[b * COUT + o] = 1.0f / sqrtf(s + 1e-8f);
}

// ============================================================
// K4: main conv.
// CTA: batch b, 4 output rows x 64 cols (256 px), 64 output channels.
// Thread (tx=t&31, ty=t>>5): 8 pixels (p = 32j+tx) x 8 ocs (oc0+ty*8+u),
// oc pairs packed into f32x2 accumulators (4 pairs).
// IC chunked by 8; smem holds modulated x tile (with halo) + weights.
// ============================================================
#define ICC 8
#define RT  4
#define OCB 64

__global__ __launch_bounds__(256) void k_conv(
    const float* __restrict__ x, const float* __restrict__ noise,
    const float* __restrict__ scale_noise, const float* __restrict__ bias,
    float* __restrict__ out)
{
    __shared__ float xs[ICC][RT + 2][68];   // halo rows (-1..+4), halo cols (-1..64)
    __shared__ float ws[ICC][9][OCB];

    int b   = blockIdx.z;
    int r0  = blockIdx.y * RT;
    int oc0 = blockIdx.x * OCB;
    int t   = threadIdx.x;
    int tx  = t & 31;
    int ty  = t >> 5;

    unsigned long long acc[8][4];
#pragma unroll
    for (int j = 0; j < 8; j++)
#pragma unroll
        for (int u = 0; u < 4; u++) acc[j][u] = 0ull;

    const float* xb = x + (size_t)b * CIN * Hs * Ws;
    const float* modb = g_mod + b * CIN;

    for (int icb = 0; icb < CIN; icb += ICC) {
        // weights: [ic_l][tap][oc_l], coalesced from g_cwt
        for (int idx = t; idx < ICC * 9 * OCB; idx += 256) {
            int ic_l = idx / (9 * OCB);
            int rem  = idx % (9 * OCB);
            int tap  = rem / OCB, oc_l = rem % OCB;
            ws[ic_l][tap][oc_l] =
                g_cwt[((icb + ic_l) * 9 + tap) * COUT + oc0 + oc_l];
        }
        // x tile (premodulated), zero-padded halo
        for (int idx = t; idx < ICC * 6 * 66; idx += 256) {
            int ic_l = idx / (6 * 66);
            int rem  = idx % (6 * 66);
            int rr = rem / 66, cc = rem % 66;
            int gr = r0 - 1 + rr, gc = cc - 1;
            float v = 0.f;
            if (gr >= 0 && gr < Hs && gc >= 0 && gc < Ws)
                v = xb[(icb + ic_l) * (Hs * Ws) + gr * Ws + gc] *
                    __ldg(&modb[icb + ic_l]);
            xs[ic_l][rr][cc] = v;
        }
        __syncthreads();

        for (int ic_l = 0; ic_l < ICC; ic_l++) {
#pragma unroll
            for (int ky = 0; ky < 3; ky++) {
#pragma unroll
                for (int kx = 0; kx < 3; kx++) {
                    unsigned long long w2[4];
#pragma unroll
                    for (int u = 0; u < 4; u++)
                        w2[u] = *(const unsigned long long*)
                                &ws[ic_l][ky * 3 + kx][ty * 8 + u * 2];
#pragma unroll
                    for (int j = 0; j < 8; j++) {
                        int row = j >> 1;
                        int col = ((j & 1) << 5) + tx;
                        float xv = xs[ic_l][row + ky][col + kx];
                        unsigned xvi = __float_as_uint(xv);
                        unsigned long long x2;
                        asm("mov.b64 %0, {%1, %1};" : "=l"(x2) : "r"(xvi));
#pragma unroll
                        for (int u = 0; u < 4; u++)
                            asm("fma.rn.f32x2 %0, %1, %2, %0;"
                                : "+l"(acc[j][u]) : "l"(x2), "l"(w2[u]));
                    }
                }
            }
        }
        __syncthreads();
    }

    // ---- epilogue: demod scale, noise, bias, leaky relu ----
    float sn = __ldg(scale_noise);
    float sigv[8], bi[8];
#pragma unroll
    for (int u = 0; u < 8; u++) {
        int oc = oc0 + ty * 8 + u;
        sigv[u] = g_sig[b * COUT + oc];
        bi[u]   = __ldg(&bias[oc]);
    }
#pragma unroll
    for (int j = 0; j < 8; j++) {
        int p   = j * 32 + tx;
        int row = r0 + (p >> 6);
        int col = p & 63;
        float nz = sn * __ldg(&noise[b * (Hs * Ws) + row * Ws + col]);
#pragma unroll
        for (int u = 0; u < 4; u++) {
            unsigned lo, hi;
            asm("mov.b64 {%0, %1}, %2;" : "=r"(lo), "=r"(hi) : "l"(acc[j][u]));
            float f0 = __uint_as_float(lo);
            float f1 = __uint_as_float(hi);
            int oc = oc0 + ty * 8 + u * 2;
            float v0 = f0 * sigv[u * 2]     + nz + bi[u * 2];
            float v1 = f1 * sigv[u * 2 + 1] + nz + bi[u * 2 + 1];
            v0 = v0 < 0.f ? 0.2f * v0 : v0;
            v1 = v1 < 0.f ? 0.2f * v1 : v1;
            size_t base = ((size_t)(b * COUT + oc)) * (Hs * Ws) + row * Ws + col;
            out[base]           = v0;
            out[base + Hs * Ws] = v1;
        }
    }
}

// ============================================================
// launch
// inputs (metadata order): x, w, noise, style_w, style_b, conv_w,
//                          scale_noise, bias
// ============================================================
extern "C" void kernel_launch(void* const* d_in, const int* in_sizes, int n_in,
                              void* d_out, int out_size)
{
    const float* x          = (const float*)d_in[0];
    const float* w          = (const float*)d_in[1];
    const float* noise      = (const float*)d_in[2];
    const float* style_w    = (const float*)d_in[3];
    const float* style_b    = (const float*)d_in[4];
    const float* conv_w     = (const float*)d_in[5];
    const float* scale_noise= (const float*)d_in[6];
    const float* bias       = (const float*)d_in[7];
    float* out = (float*)d_out;

    k_style<<<CIN / 16, 256>>>(w, style_w, style_b);
    k_transpose<<<dim3(9, CIN), COUT>>>(conv_w);
    k_wsq<<<CIN, COUT>>>();
    k_sig<<<B_, COUT>>>();
    k_conv<<<dim3(COUT / OCB, Hs / RT, B_), 256>>>(x, noise, scale_noise, bias, out);
}

// round 5
// speedup vs baseline: 2.5125x; 2.5125x over previous
#include <cuda_runtime.h>
#include <cuda_bf16.h>
#include <cstdint>

#define B_    16
#define CIN   512
#define COUT  512
#define DLAT  512
#define Hs    64
#define Ws    64
#define NPIX  (Hs*Ws)

#define LIN_COEF  0.04419417382415922f    // 1/sqrt(512)
#define CONV_COEF 0.014731391274719742f   // 1/sqrt(512*9)

// ---------------- device scratch (no allocation allowed) ----------------
__device__ float g_mod[B_ * CIN];
__device__ float g_sig[B_ * COUT];
__device__ float g_cwt[CIN * 9 * COUT];
__device__ float g_wsqT[CIN * COUT];
__device__ __nv_bfloat16 g_xh[(size_t)B_ * NPIX * CIN];   // NHWC hi
__device__ __nv_bfloat16 g_xl[(size_t)B_ * NPIX * CIN];   // NHWC lo
__device__ __nv_bfloat16 g_wh[9 * COUT * CIN];            // [tap][o][i] hi
__device__ __nv_bfloat16 g_wl[9 * COUT * CIN];            // [tap][o][i] lo

#define SWZ(o) ((o) ^ (((o) >> 3) & 0x70))

__device__ __forceinline__ uint32_t smem_u32(const void* p) {
    uint32_t a;
    asm("{ .reg .u64 t; cvta.to.shared.u64 t, %1; cvt.u32.u64 %0, t; }"
        : "=r"(a) : "l"(p));
    return a;
}

// ============================================================
// K1: style modulation
// ============================================================
__global__ __launch_bounds__(256) void k_style(
    const float* __restrict__ w, const float* __restrict__ sw,
    const float* __restrict__ sb)
{
    __shared__ float s_sw[16][DLAT + 1];
    int i0 = blockIdx.x * 16;
    for (int idx = threadIdx.x; idx < 16 * DLAT; idx += 256) {
        int r = idx / DLAT, d = idx % DLAT;
        s_sw[r][d] = sw[(i0 + r) * DLAT + d];
    }
    __syncthreads();
    int t = threadIdx.x;
    int b = t >> 4, il = t & 15;
    const float* wb = w + b * DLAT;
    float acc = 0.f;
    for (int d = 0; d < DLAT; d++) acc += __ldg(&wb[d]) * s_sw[il][d];
    int i = i0 + il;
    g_mod[b * CIN + i] = (acc * LIN_COEF + sb[i]) * CONV_COEF;
}

// K2a: transpose conv_w -> g_cwt [i][tap][o]
__global__ __launch_bounds__(512) void k_transpose(const float* __restrict__ cw)
{
    int tap = blockIdx.x, i = blockIdx.y, o = threadIdx.x;
    g_cwt[(i * 9 + tap) * COUT + o] = cw[(o * CIN + i) * 9 + tap];
}

// K2b: wsqT[i][o]
__global__ __launch_bounds__(512) void k_wsq()
{
    int i = blockIdx.x, o = threadIdx.x;
    float s = 0.f;
#pragma unroll
    for (int tap = 0; tap < 9; tap++) {
        float v = g_cwt[(i * 9 + tap) * COUT + o];
        s += v * v;
    }
    g_wsqT[i * COUT + o] = s;
}

// K3: sigma_inv
__global__ __launch_bounds__(512) void k_sig()
{
    __shared__ float m2[CIN];
    int b = blockIdx.x, o = threadIdx.x;
    for (int i = threadIdx.x; i < CIN; i += 512) {
        float m = g_mod[b * CIN + i];
        m2[i] = m * m;
    }
    __syncthreads();
    float s = 0.f;
    for (int i = 0; i < CIN; i++) s += m2[i] * g_wsqT[i * COUT + o];
    g_sig[b * COUT + o] = 1.0f / sqrtf(s + 1e-8f);
}

// K4: weight split  conv_w[o][i][tap] -> g_wh/g_wl [tap][o][i]
__global__ __launch_bounds__(256) void k_wsplit(const float* __restrict__ cw)
{
    int o = blockIdx.x;
    for (int i = threadIdx.x; i < CIN; i += 256) {
        const float* p = cw + ((size_t)o * CIN + i) * 9;
#pragma unroll
        for (int tap = 0; tap < 9; tap++) {
            float v = p[tap];
            __nv_bfloat16 h = __float2bfloat16(v);
            __nv_bfloat16 l = __float2bfloat16(v - __bfloat162float(h));
            size_t di = ((size_t)tap * COUT + o) * CIN + i;
            g_wh[di] = h;
            g_wl[di] = l;
        }
    }
}

// K5: x modulate + CHW->HWC transpose + bf16 split
__global__ __launch_bounds__(256) void k_xsplit(const float* __restrict__ x)
{
    __shared__ float t[64][65];
    int b = blockIdx.z, i0 = blockIdx.y * 64, p0 = blockIdx.x * 64;
    for (int idx = threadIdx.x; idx < 4096; idx += 256) {
        int ii = idx >> 6, pp = idx & 63;
        t[ii][pp] = x[((size_t)b * CIN + i0 + ii) * NPIX + p0 + pp] *
                    g_mod[b * CIN + i0 + ii];
    }
    __syncthreads();
    for (int idx = threadIdx.x; idx < 4096; idx += 256) {
        int pp = idx >> 6, ii = idx & 63;
        float v = t[ii][pp];
        __nv_bfloat16 h = __float2bfloat16(v);
        __nv_bfloat16 l = __float2bfloat16(v - __bfloat162float(h));
        size_t di = ((size_t)b * NPIX + p0 + pp) * CIN + i0 + ii;
        g_xh[di] = h;
        g_xl[di] = l;
    }
}

// ============================================================
// K6: main conv via mma.sync bf16 3-pass split GEMM
// CTA 128oc x 128px, K staged in 64ic chunks x 9 taps (72 stages),
// double-buffered cp.async, SW128-swizzled smem, ldmatrix feeds.
// Warp grid 4(M) x 2(N): warp tile 32oc x 64px.
// smem buffer (per stage): A 2pl x 128 x 128B (32KB) + B same (32KB).
// ============================================================
#define BUFB  65536
#define DSMEM (2 * BUFB)

#define MMA_BF16(c, a, b0, b1)                                               \
    asm volatile("mma.sync.aligned.m16n8k16.row.col.f32.bf16.bf16.f32 "      \
        "{%0,%1,%2,%3}, {%4,%5,%6,%7}, {%8,%9}, {%0,%1,%2,%3};"              \
        : "+f"((c)[0]), "+f"((c)[1]), "+f"((c)[2]), "+f"((c)[3])             \
        : "r"((a)[0]), "r"((a)[1]), "r"((a)[2]), "r"((a)[3]),                \
          "r"(b0), "r"(b1))

#define LDSM4(r, addr)                                                       \
    asm volatile("ldmatrix.sync.aligned.m8n8.x4.shared.b16 "                 \
        "{%0,%1,%2,%3}, [%4];"                                               \
        : "=r"((r)[0]), "=r"((r)[1]), "=r"((r)[2]), "=r"((r)[3])             \
        : "r"(addr))

__global__ __launch_bounds__(256, 1) void k_conv_hmma(
    const float* __restrict__ noise, const float* __restrict__ scale_noise,
    const float* __restrict__ bias, float* __restrict__ out)
{
    extern __shared__ __align__(1024) char dsm[];
    uint32_t sbase = smem_u32(dsm);

    int tid = threadIdx.x;
    int lane = tid & 31, wid = tid >> 5;
    int wm = wid >> 1, wn = wid & 1;
    int b    = blockIdx.z;
    int oc0  = blockIdx.x * 128;
    int pix0 = blockIdx.y * 128;
    int pr0  = blockIdx.y * 2;

    // --- precomputed ldmatrix lane address components ---
    // A: x4 tiles: lanes 0-7 rows m0..7 (k lo 16B), 8-15 rows m8..15,
    //    16-23 rows m0..7 (+16B), 24-31 rows m8..15 (+16B)
    int selA = ((lane >> 4) & 1) * 16;
    uint32_t rbA[2], mkA[2];
#pragma unroll
    for (int mt = 0; mt < 2; mt++) {
        int row = wm * 32 + mt * 16 + (lane & 15);
        rbA[mt] = row * 128;
        mkA[mt] = (rbA[mt] >> 3) & 0x70;
    }
    // B: x4 over two n-tiles: lanes 0-7 n0..7 (klo), 8-15 n0..7 (khi),
    //    16-23 n8..15 (klo), 24-31 n8..15 (khi)
    int selB = ((lane >> 3) & 1) * 16;
    uint32_t rbB[4], mkB[4];
#pragma unroll
    for (int j = 0; j < 4; j++) {
        int row = wn * 64 + j * 16 + (lane & 7) + ((lane >> 4) & 1) * 8;
        rbB[j] = row * 128;
        mkB[j] = (rbB[j] >> 3) & 0x70;
    }

    float acc[2][8][4];
#pragma unroll
    for (int mt = 0; mt < 2; mt++)
#pragma unroll
        for (int nt = 0; nt < 8; nt++)
#pragma unroll
            for (int q = 0; q < 4; q++) acc[mt][nt][q] = 0.f;

    // ---------------- stage loader (cp.async, 16 chunks/thread) -------------
    auto stage_load = [&](int s) {
        int tap = s >> 3, ic0 = (s & 7) << 6;
        int dy = tap / 3 - 1, dx = tap % 3 - 1;
        uint32_t base = sbase + (s & 1) * BUFB;
        // A: [plane][row 0..127][8 x 16B]
#pragma unroll
        for (int k = 0; k < 8; k++) {
            int idx = tid + k * 256;
            int plane = idx >> 10;
            int rem = idx & 1023;
            int row = rem >> 3, cb = rem & 7;
            const __nv_bfloat16* g = (plane ? g_wl : g_wh) +
                ((size_t)tap * COUT + oc0 + row) * CIN + ic0 + cb * 8;
            uint32_t d = base + plane * 16384 + SWZ((uint32_t)(row * 128 + cb * 16));
            asm volatile("cp.async.cg.shared.global [%0], [%1], 16;"
                         :: "r"(d), "l"(g));
        }
        // B: shifted window with zero fill
#pragma unroll
        for (int k = 0; k < 8; k++) {
            int idx = tid + k * 256;
            int plane = idx >> 10;
            int rem = idx & 1023;
            int n = rem >> 3, cb = rem & 7;
            int r = pr0 + (n >> 6) + dy;
            int c = (n & 63) + dx;
            int ok = ((unsigned)r < Hs) && ((unsigned)c < Ws);
            int rc = ok ? r : 0, cc = ok ? c : 0;
            const __nv_bfloat16* g = (plane ? g_xl : g_xh) +
                ((size_t)b * NPIX + rc * Ws + cc) * CIN + ic0 + cb * 8;
            uint32_t d = base + 32768 + plane * 16384 +
                         SWZ((uint32_t)(n * 128 + cb * 16));
            int sz = ok ? 16 : 0;
            asm volatile("cp.async.cg.shared.global [%0], [%1], 16, %2;"
                         :: "r"(d), "l"(g), "r"(sz));
        }
        asm volatile("cp.async.commit_group;");
    };

    stage_load(0);

    for (int s = 0; s < 72; s++) {
        if (s < 71) {
            stage_load(s + 1);
            asm volatile("cp.async.wait_group 1;");
        } else {
            asm volatile("cp.async.wait_group 0;");
        }
        __syncthreads();

        uint32_t abuf = sbase + (s & 1) * BUFB;
        uint32_t bbuf = abuf + 32768;

#pragma unroll
        for (int kk = 0; kk < 4; kk++) {
            uint32_t aF[2][2][4];   // [plane][mt]
            uint32_t bF[2][4][4];   // [plane][jpair] -> {b0,b1 of nt 2j; b0,b1 of nt 2j+1}
            int col = kk * 32;
#pragma unroll
            for (int pl = 0; pl < 2; pl++) {
#pragma unroll
                for (int mt = 0; mt < 2; mt++) {
                    uint32_t a = abuf + pl * 16384 + rbA[mt] +
                                 (uint32_t)((col + selA) ^ mkA[mt]);
                    LDSM4(aF[pl][mt], a);
                }
#pragma unroll
                for (int j = 0; j < 4; j++) {
                    uint32_t a = bbuf + pl * 16384 + rbB[j] +
                                 (uint32_t)((col + selB) ^ mkB[j]);
                    LDSM4(bF[pl][j], a);
                }
            }
            // 3 passes: hh, hl, lh
#pragma unroll
            for (int pass = 0; pass < 3; pass++) {
                int pa = (pass == 2) ? 1 : 0;
                int pb = (pass == 1) ? 1 : 0;
#pragma unroll
                for (int mt = 0; mt < 2; mt++) {
#pragma unroll
                    for (int nt = 0; nt < 8; nt++) {
                        int j = nt >> 1, lo = (nt & 1) * 2;
                        MMA_BF16(acc[mt][nt], aF[pa][mt],
                                 bF[pb][j][lo], bF[pb][j][lo + 1]);
                    }
                }
            }
        }
        __syncthreads();
    }

    // ---------------- epilogue: demod, noise, bias, leaky relu --------------
    float sn = __ldg(scale_noise);
#pragma unroll
    for (int mt = 0; mt < 2; mt++) {
        int oc_lo = oc0 + wm * 32 + mt * 16 + (lane >> 2);
        float sg0 = g_sig[b * COUT + oc_lo];
        float sg1 = g_sig[b * COUT + oc_lo + 8];
        float bi0 = __ldg(&bias[oc_lo]);
        float bi1 = __ldg(&bias[oc_lo + 8]);
#pragma unroll
        for (int nt = 0; nt < 8; nt++) {
            int n = wn * 64 + nt * 8 + (lane & 3) * 2;
            int p = pix0 + n;
            float2 nz = *(const float2*)&noise[(size_t)b * NPIX + p];
            float n0 = sn * nz.x, n1 = sn * nz.y;

            float v0 = acc[mt][nt][0] * sg0 + n0 + bi0;
            float v1 = acc[mt][nt][1] * sg0 + n1 + bi0;
            float v2 = acc[mt][nt][2] * sg1 + n0 + bi1;
            float v3 = acc[mt][nt][3] * sg1 + n1 + bi1;
            v0 = v0 < 0.f ? 0.2f * v0 : v0;
            v1 = v1 < 0.f ? 0.2f * v1 : v1;
            v2 = v2 < 0.f ? 0.2f * v2 : v2;
            v3 = v3 < 0.f ? 0.2f * v3 : v3;

            float2 w0 = make_float2(v0, v1);
            float2 w1 = make_float2(v2, v3);
            *(float2*)&out[((size_t)(b * COUT + oc_lo)) * NPIX + p]     = w0;
            *(float2*)&out[((size_t)(b * COUT + oc_lo + 8)) * NPIX + p] = w1;
        }
    }
}

// ============================================================
// launch: x, w, noise, style_w, style_b, conv_w, scale_noise, bias
// ============================================================
extern "C" void kernel_launch(void* const* d_in, const int* in_sizes, int n_in,
                              void* d_out, int out_size)
{
    const float* x           = (const float*)d_in[0];
    const float* w           = (const float*)d_in[1];
    const float* noise       = (const float*)d_in[2];
    const float* style_w     = (const float*)d_in[3];
    const float* style_b     = (const float*)d_in[4];
    const float* conv_w      = (const float*)d_in[5];
    const float* scale_noise = (const float*)d_in[6];
    const float* bias        = (const float*)d_in[7];
    float* out = (float*)d_out;

    cudaFuncSetAttribute(k_conv_hmma,
                         cudaFuncAttributeMaxDynamicSharedMemorySize, DSMEM);

    k_style<<<CIN / 16, 256>>>(w, style_w, style_b);
    k_transpose<<<dim3(9, CIN), COUT>>>(conv_w);
    k_wsq<<<CIN, COUT>>>();
    k_sig<<<B_, COUT>>>();
    k_wsplit<<<COUT, 256>>>(conv_w);
    k_xsplit<<<dim3(64, 8, B_), 256>>>(x);
    k_conv_hmma<<<dim3(4, 32, B_), 256, DSMEM>>>(noise, scale_noise, bias, out);
}

// round 6
// speedup vs baseline: 2.9129x; 1.1593x over previous
#include <cuda_runtime.h>
#include <cuda_bf16.h>
#include <cstdint>

#define B_    16
#define CIN   512
#define COUT  512
#define DLAT  512
#define Hs    64
#define Ws    64
#define NPIX  (Hs*Ws)

#define LIN_COEF  0.04419417382415922f    // 1/sqrt(512)
#define CONV_COEF 0.014731391274719742f   // 1/sqrt(512*9)

// ---------------- device scratch (no allocation allowed) ----------------
__device__ float g_mod[B_ * CIN];
__device__ float g_sig[B_ * COUT];
__device__ float g_cwt[CIN * 9 * COUT];
__device__ float g_wsqT[CIN * COUT];
__device__ __nv_bfloat16 g_xh[(size_t)B_ * NPIX * CIN];   // NHWC hi
__device__ __nv_bfloat16 g_xl[(size_t)B_ * NPIX * CIN];   // NHWC lo
__device__ __nv_bfloat16 g_wh[9 * COUT * CIN];            // [tap][o][i] hi
__device__ __nv_bfloat16 g_wl[9 * COUT * CIN];            // [tap][o][i] lo

__device__ __forceinline__ uint32_t smem_u32(const void* p) {
    uint32_t a;
    asm("{ .reg .u64 t; cvta.to.shared.u64 t, %1; cvt.u32.u64 %0, t; }"
        : "=r"(a) : "l"(p));
    return a;
}

// ============================================================
// K1: style modulation
// ============================================================
__global__ __launch_bounds__(256) void k_style(
    const float* __restrict__ w, const float* __restrict__ sw,
    const float* __restrict__ sb)
{
    __shared__ float s_sw[16][DLAT + 1];
    int i0 = blockIdx.x * 16;
    for (int idx = threadIdx.x; idx < 16 * DLAT; idx += 256) {
        int r = idx / DLAT, d = idx % DLAT;
        s_sw[r][d] = sw[(i0 + r) * DLAT + d];
    }
    __syncthreads();
    int t = threadIdx.x;
    int b = t >> 4, il = t & 15;
    const float* wb = w + b * DLAT;
    float acc = 0.f;
    for (int d = 0; d < DLAT; d++) acc += __ldg(&wb[d]) * s_sw[il][d];
    int i = i0 + il;
    g_mod[b * CIN + i] = (acc * LIN_COEF + sb[i]) * CONV_COEF;
}

// K2a: transpose conv_w -> g_cwt [i][tap][o]
__global__ __launch_bounds__(512) void k_transpose(const float* __restrict__ cw)
{
    int tap = blockIdx.x, i = blockIdx.y, o = threadIdx.x;
    g_cwt[(i * 9 + tap) * COUT + o] = cw[(o * CIN + i) * 9 + tap];
}

// K2b: wsqT[i][o]
__global__ __launch_bounds__(512) void k_wsq()
{
    int i = blockIdx.x, o = threadIdx.x;
    float s = 0.f;
#pragma unroll
    for (int tap = 0; tap < 9; tap++) {
        float v = g_cwt[(i * 9 + tap) * COUT + o];
        s += v * v;
    }
    g_wsqT[i * COUT + o] = s;
}

// K3: sigma_inv
__global__ __launch_bounds__(512) void k_sig()
{
    __shared__ float m2[CIN];
    int b = blockIdx.x, o = threadIdx.x;
    for (int i = threadIdx.x; i < CIN; i += 512) {
        float m = g_mod[b * CIN + i];
        m2[i] = m * m;
    }
    __syncthreads();
    float s = 0.f;
    for (int i = 0; i < CIN; i++) s += m2[i] * g_wsqT[i * COUT + o];
    g_sig[b * COUT + o] = 1.0f / sqrtf(s + 1e-8f);
}

// K4: weight split  conv_w[o][i][tap] -> g_wh/g_wl [tap][o][i]
__global__ __launch_bounds__(256) void k_wsplit(const float* __restrict__ cw)
{
    int o = blockIdx.x;
    for (int i = threadIdx.x; i < CIN; i += 256) {
        const float* p = cw + ((size_t)o * CIN + i) * 9;
#pragma unroll
        for (int tap = 0; tap < 9; tap++) {
            float v = p[tap];
            __nv_bfloat16 h = __float2bfloat16(v);
            __nv_bfloat16 l = __float2bfloat16(v - __bfloat162float(h));
            size_t di = ((size_t)tap * COUT + o) * CIN + i;
            g_wh[di] = h;
            g_wl[di] = l;
        }
    }
}

// K5: x modulate + CHW->HWC transpose + bf16 split
__global__ __launch_bounds__(256) void k_xsplit(const float* __restrict__ x)
{
    __shared__ float t[64][65];
    int b = blockIdx.z, i0 = blockIdx.y * 64, p0 = blockIdx.x * 64;
    for (int idx = threadIdx.x; idx < 4096; idx += 256) {
        int ii = idx >> 6, pp = idx & 63;
        t[ii][pp] = x[((size_t)b * CIN + i0 + ii) * NPIX + p0 + pp] *
                    g_mod[b * CIN + i0 + ii];
    }
    __syncthreads();
    for (int idx = threadIdx.x; idx < 4096; idx += 256) {
        int pp = idx >> 6, ii = idx & 63;
        float v = t[ii][pp];
        __nv_bfloat16 h = __float2bfloat16(v);
        __nv_bfloat16 l = __float2bfloat16(v - __bfloat162float(h));
        size_t di = ((size_t)b * NPIX + p0 + pp) * CIN + i0 + ii;
        g_xh[di] = h;
        g_xl[di] = l;
    }
}

// ============================================================
// K6: conv as bf16 3-pass split GEMM, halo-resident B.
// CTA 128oc x 256px (4 image rows), 512 thr, warp grid 4(M)x4(N),
// warp tile 32oc x 64px.
// B: one 64-ic chunk, halo 6 rows x 66 cols x 2 planes (resident for 9 taps)
// A: per (tap, ic) stage, 2 planes x 128oc x 128B, triple-buffered cp.async.
// ============================================================
#define BH_ROWS 6
#define BH_COLS 66
#define BH_PX   (BH_ROWS * BH_COLS)      // 396
#define BPL     (BH_PX * 128)            // 50688 per plane
#define A_STG   32768                    // per A stage (2 planes x 16KB)
#define B_OFF   (3 * A_STG)              // 98304
#define DSMEM   (B_OFF + 2 * BPL)        // 199680

#define MMA_BF16(c, a, b0, b1)                                               \
    asm volatile("mma.sync.aligned.m16n8k16.row.col.f32.bf16.bf16.f32 "      \
        "{%0,%1,%2,%3}, {%4,%5,%6,%7}, {%8,%9}, {%0,%1,%2,%3};"              \
        : "+f"((c)[0]), "+f"((c)[1]), "+f"((c)[2]), "+f"((c)[3])             \
        : "r"((a)[0]), "r"((a)[1]), "r"((a)[2]), "r"((a)[3]),                \
          "r"(b0), "r"(b1))

#define LDSM4(r, addr)                                                       \
    asm volatile("ldmatrix.sync.aligned.m8n8.x4.shared.b16 "                 \
        "{%0,%1,%2,%3}, [%4];"                                               \
        : "=r"((r)[0]), "=r"((r)[1]), "=r"((r)[2]), "=r"((r)[3])             \
        : "r"(addr))

__global__ __launch_bounds__(512, 1) void k_conv_hmma(
    const float* __restrict__ noise, const float* __restrict__ scale_noise,
    const float* __restrict__ bias, float* __restrict__ out)
{
    extern __shared__ __align__(1024) char dsm[];
    uint32_t sbase = smem_u32(dsm);

    int tid = threadIdx.x;
    int lane = tid & 31, wid = tid >> 5;
    int wm = wid >> 2, wn = wid & 3;
    int b    = blockIdx.z;
    int oc0  = blockIdx.x * 128;
    int pix0 = blockIdx.y * 256;
    int pr0  = blockIdx.y * 4;

    // A ldmatrix lane components
    int selA = ((lane >> 4) & 1) * 16;
    uint32_t rbA[2], mkA[2];
#pragma unroll
    for (int mt = 0; mt < 2; mt++) {
        int row = wm * 32 + mt * 16 + (lane & 15);
        rbA[mt] = row * 128;
        mkA[mt] = (uint32_t)(row & 7) << 4;
    }
    // B lane pixel decomposition (image-row, image-col of this lane's n)
    int selB = ((lane >> 3) & 1) * 16;
    int irB[4], icB[4];
#pragma unroll
    for (int j = 0; j < 4; j++) {
        int n = wn * 64 + j * 16 + (lane & 7) + ((lane >> 4) & 1) * 8;
        irB[j] = n >> 6;
        icB[j] = n & 63;
    }

    float acc[2][8][4];
#pragma unroll
    for (int mt = 0; mt < 2; mt++)
#pragma unroll
        for (int nt = 0; nt < 8; nt++)
#pragma unroll
            for (int q = 0; q < 4; q++) acc[mt][nt][q] = 0.f;

    // ---- A stage loader: (tap, ic chunk) -> buffer ----
    auto load_A = [&](int tapv, int icv, int buf) {
#pragma unroll
        for (int k = 0; k < 4; k++) {
            int idx = tid + k * 512;
            int plane = idx >> 10;
            int rem = idx & 1023;
            int row = rem >> 3, cb = rem & 7;
            const __nv_bfloat16* g = (plane ? g_wl : g_wh) +
                ((size_t)tapv * COUT + oc0 + row) * CIN + icv * 64 + cb * 8;
            uint32_t d = sbase + buf * A_STG + plane * 16384 +
                         (uint32_t)(row * 128) + (uint32_t)((cb * 16) ^ ((row & 7) << 4));
            asm volatile("cp.async.cg.shared.global [%0], [%1], 16;"
                         :: "r"(d), "l"(g));
        }
        asm volatile("cp.async.commit_group;");
    };

    // ---- B halo loader for ic chunk ----
    auto load_B = [&](int icv) {
        for (int idx = tid; idx < BH_PX * 8; idx += 512) {
            int px = idx >> 3, cb = idx & 7;
            int hrow = px / BH_COLS;
            int hcol = px - hrow * BH_COLS;
            int r = pr0 - 1 + hrow;
            int c = hcol - 1;
            int ok = ((unsigned)r < Hs) && ((unsigned)c < Ws);
            size_t gofs = ((size_t)b * NPIX + (ok ? r * Ws + c : 0)) * CIN +
                          icv * 64 + cb * 8;
            uint32_t dofs = (uint32_t)(px * 128) +
                            (uint32_t)((cb * 16) ^ ((px & 7) << 4));
            int sz = ok ? 16 : 0;
            {
                uint32_t d = sbase + B_OFF + dofs;
                const __nv_bfloat16* g = g_xh + gofs;
                asm volatile("cp.async.cg.shared.global [%0], [%1], 16, %2;"
                             :: "r"(d), "l"(g), "r"(sz));
            }
            {
                uint32_t d = sbase + B_OFF + BPL + dofs;
                const __nv_bfloat16* g = g_xl + gofs;
                asm volatile("cp.async.cg.shared.global [%0], [%1], 16, %2;"
                             :: "r"(d), "l"(g), "r"(sz));
            }
        }
        asm volatile("cp.async.commit_group;");
    };

    // ---- prologue: B(0), A(0), A(1) ----
    load_B(0);
    load_A(0, 0, 0);
    load_A(1, 0, 1);

    int s = 0;
    int ntap = 2, nic = 0;    // next A stage to fetch
    for (int ic = 0; ic < 8; ic++) {
        for (int tap = 0; tap < 9; tap++, s++) {
            if (tap == 0) {
                __syncthreads();                  // B buffer + A buf reuse safe
                if (ic > 0) load_B(ic);
                if (s < 70) {
                    load_A(ntap, nic, (s + 2) % 3);
                    if (++ntap == 9) { ntap = 0; nic++; }
                }
                asm volatile("cp.async.wait_group 0;");
                __syncthreads();
            } else {
                if (s >= 70)
                    asm volatile("cp.async.wait_group 0;");
                else
                    asm volatile("cp.async.wait_group 1;");
                __syncthreads();
                if (s < 70) {
                    load_A(ntap, nic, (s + 2) % 3);
                    if (++ntap == 9) { ntap = 0; nic++; }
                }
            }

            // ---- compute stage s: A buffer s%3, B halo with tap shift ----
            uint32_t abuf = sbase + (s % 3) * A_STG;
            int dy = tap / 3 - 1, dx = tap % 3 - 1;
            uint32_t rowB[4], mskB[4];
#pragma unroll
            for (int j = 0; j < 4; j++) {
                int rp = (irB[j] + 1 + dy) * BH_COLS + icB[j] + 1 + dx;
                rowB[j] = (uint32_t)(rp * 128);
                mskB[j] = (uint32_t)(rp & 7) << 4;
            }

#pragma unroll
            for (int kk = 0; kk < 4; kk++) {
                uint32_t aF[2][2][4];
                uint32_t bF[2][4][4];
                int col = kk * 32;
#pragma unroll
                for (int pl = 0; pl < 2; pl++) {
#pragma unroll
                    for (int mt = 0; mt < 2; mt++) {
                        uint32_t a = abuf + pl * 16384 + rbA[mt] +
                                     (uint32_t)((col + selA) ^ mkA[mt]);
                        LDSM4(aF[pl][mt], a);
                    }
#pragma unroll
                    for (int j = 0; j < 4; j++) {
                        uint32_t a = sbase + B_OFF + pl * BPL + rowB[j] +
                                     (uint32_t)((col + selB) ^ mskB[j]);
                        LDSM4(bF[pl][j], a);
                    }
                }
                // 3 passes: hh, hl, lh
#pragma unroll
                for (int pass = 0; pass < 3; pass++) {
                    int pa = (pass == 2) ? 1 : 0;
                    int pb = (pass == 1) ? 1 : 0;
#pragma unroll
                    for (int mt = 0; mt < 2; mt++) {
#pragma unroll
                        for (int nt = 0; nt < 8; nt++) {
                            int j = nt >> 1, lo = (nt & 1) * 2;
                            MMA_BF16(acc[mt][nt], aF[pa][mt],
                                     bF[pb][j][lo], bF[pb][j][lo + 1]);
                        }
                    }
                }
            }
        }
    }

    // ---------------- epilogue ----------------
    float sn = __ldg(scale_noise);
#pragma unroll
    for (int mt = 0; mt < 2; mt++) {
        int oc_lo = oc0 + wm * 32 + mt * 16 + (lane >> 2);
        float sg0 = g_sig[b * COUT + oc_lo];
        float sg1 = g_sig[b * COUT + oc_lo + 8];
        float bi0 = __ldg(&bias[oc_lo]);
        float bi1 = __ldg(&bias[oc_lo + 8]);
#pragma unroll
        for (int nt = 0; nt < 8; nt++) {
            int p = pix0 + wn * 64 + nt * 8 + (lane & 3) * 2;
            float2 nz = *(const float2*)&noise[(size_t)b * NPIX + p];
            float n0 = sn * nz.x, n1 = sn * nz.y;

            float v0 = acc[mt][nt][0] * sg0 + n0 + bi0;
            float v1 = acc[mt][nt][1] * sg0 + n1 + bi0;
            float v2 = acc[mt][nt][2] * sg1 + n0 + bi1;
            float v3 = acc[mt][nt][3] * sg1 + n1 + bi1;
            v0 = v0 < 0.f ? 0.2f * v0 : v0;
            v1 = v1 < 0.f ? 0.2f * v1 : v1;
            v2 = v2 < 0.f ? 0.2f * v2 : v2;
            v3 = v3 < 0.f ? 0.2f * v3 : v3;

            *(float2*)&out[((size_t)(b * COUT + oc_lo)) * NPIX + p] =
                make_float2(v0, v1);
            *(float2*)&out[((size_t)(b * COUT + oc_lo + 8)) * NPIX + p] =
                make_float2(v2, v3);
        }
    }
}

// ============================================================
// launch: x, w, noise, style_w, style_b, conv_w, scale_noise, bias
// ============================================================
extern "C" void kernel_launch(void* const* d_in, const int* in_sizes, int n_in,
                              void* d_out, int out_size)
{
    const float* x           = (const float*)d_in[0];
    const float* w           = (const float*)d_in[1];
    const float* noise       = (const float*)d_in[2];
    const float* style_w     = (const float*)d_in[3];
    const float* style_b     = (const float*)d_in[4];
    const float* conv_w      = (const float*)d_in[5];
    const float* scale_noise = (const float*)d_in[6];
    const float* bias        = (const float*)d_in[7];
    float* out = (float*)d_out;

    cudaFuncSetAttribute(k_conv_hmma,
                         cudaFuncAttributeMaxDynamicSharedMemorySize, DSMEM);

    k_style<<<CIN / 16, 256>>>(w, style_w, style_b);
    k_transpose<<<dim3(9, CIN), COUT>>>(conv_w);
    k_wsq<<<CIN, COUT>>>();
    k_sig<<<B_, COUT>>>();
    k_wsplit<<<COUT, 256>>>(conv_w);
    k_xsplit<<<dim3(64, 8, B_), 256>>>(x);
    k_conv_hmma<<<dim3(4, 16, B_), 512, DSMEM>>>(noise, scale_noise, bias, out);
}